// round 3
// baseline (speedup 1.0000x reference)
#include <cuda_runtime.h>

// ---------------------------------------------------------------------------
// DGLossVer2: fused gyro (SO3 chain) + gaussian-NLL scalar loss.
// N=128 sequences, T=16384 steps, 3 channels.
// One warp handles 32 consecutive timesteps of one sequence:
//   lane l: R_l = exp(DT * w_hat[t0+l])
//   4 shfl_down log-steps reproduce the reference's binary-tree pairwise
//   product: lane 0 -> Q0 = R0..R15, lane 16 -> Q1 = R16..R31.
//   rs16 = log(Q^T P) at lanes 0/16, rs32 = log((Q0 Q1)^T (P0 P1)) at lane 0.
//   GNLL fused elementwise on all lanes.
// ---------------------------------------------------------------------------

#define FULL_MASK 0xFFFFFFFFu

static __device__ double g_acc[64];

struct Mat3 { float a[9]; };   // row-major a[3*i+j]

__device__ __forceinline__ Mat3 mat_mul(const Mat3& A, const Mat3& B) {
    Mat3 C;
#pragma unroll
    for (int i = 0; i < 3; i++)
#pragma unroll
        for (int j = 0; j < 3; j++)
            C.a[3*i+j] = A.a[3*i+0]*B.a[0+j] + A.a[3*i+1]*B.a[3+j] + A.a[3*i+2]*B.a[6+j];
    return C;
}

// C = A^T * B
__device__ __forceinline__ Mat3 mat_tmul(const Mat3& A, const Mat3& B) {
    Mat3 C;
#pragma unroll
    for (int i = 0; i < 3; i++)
#pragma unroll
        for (int j = 0; j < 3; j++)
            C.a[3*i+j] = A.a[0+i]*B.a[0+j] + A.a[3+i]*B.a[3+j] + A.a[6+i]*B.a[6+j];
    return C;
}

__device__ __forceinline__ Mat3 shfl_down_mat(const Mat3& M, int d) {
    Mat3 R;
#pragma unroll
    for (int i = 0; i < 9; i++) R.a[i] = __shfl_down_sync(FULL_MASK, M.a[i], d);
    return R;
}

__device__ __forceinline__ Mat3 shfl_idx_mat(const Mat3& M, int src) {
    Mat3 R;
#pragma unroll
    for (int i = 0; i < 9; i++) R.a[i] = __shfl_sync(FULL_MASK, M.a[i], src);
    return R;
}

// Rodrigues, matching reference branch structure
__device__ __forceinline__ Mat3 so3_exp(float x, float y, float z) {
    float a2 = x*x + y*y + z*z;
    float sin_t, cos_t;
    if (a2 < 1e-12f) {
        sin_t = 1.0f - a2 * (1.0f/6.0f);
        cos_t = 0.5f - a2 * (1.0f/24.0f);
    } else {
        float a = sqrtf(a2);
        sin_t = sinf(a) / a;
        cos_t = (1.0f - cosf(a)) / a2;
    }
    Mat3 R;
    float xy = x*y, xz = x*z, yz = y*z;
    R.a[0] = 1.0f + cos_t * (-(y*y + z*z));
    R.a[1] = -sin_t*z + cos_t*xy;
    R.a[2] =  sin_t*y + cos_t*xz;
    R.a[3] =  sin_t*z + cos_t*xy;
    R.a[4] = 1.0f + cos_t * (-(x*x + z*z));
    R.a[5] = -sin_t*x + cos_t*yz;
    R.a[6] = -sin_t*y + cos_t*xz;
    R.a[7] =  sin_t*x + cos_t*yz;
    R.a[8] = 1.0f + cos_t * (-(x*x + y*y));
    return R;
}

// log: matches reference (cos clipped into [-1+1e-6, 1-1e-6], so the "small"
// branch angle/2sin form is always used)
__device__ __forceinline__ void so3_log_vec(const Mat3& R, float r[3]) {
    float tr = R.a[0] + R.a[4] + R.a[8];
    float c = 0.5f * (tr - 1.0f);
    c = fminf(fmaxf(c, -1.0f + 1e-6f), 1.0f - 1e-6f);
    float ang = acosf(c);
    float factor = ang / (2.0f * sinf(ang));
    r[0] = factor * (R.a[7] - R.a[5]);
    r[1] = factor * (R.a[2] - R.a[6]);
    r[2] = factor * (R.a[3] - R.a[1]);
}

// huber( r / HUBER ) summed over 3 components; HUBER = 0.005
__device__ __forceinline__ float huber3(const float r[3]) {
    float s = 0.0f;
#pragma unroll
    for (int c = 0; c < 3; c++) {
        float x = fabsf(r[c]) * 200.0f;      // 1/HUBER
        s += (x < 1.0f) ? 0.5f * x * x : x - 0.5f;
    }
    return s;
}

// Scale constants (pre-folded means):
//  gyro16: W*H^2 / (128*1019*3)         = 25 / 391296
//  gyro32: W*H^2 / 4 / (128*507*3)      = 6.25 / 194688
//  gnll:   0.5 / (128*16384*3)
#define C16  (25.0 / 391296.0)
#define C32  (6.25 / 194688.0)
#define CNLL (0.5 / 6291456.0)

__global__ void zero_acc_kernel() {
    if (threadIdx.x < 64) g_acc[threadIdx.x] = 0.0;
}

__global__ void __launch_bounds__(256)
loss_kernel(const float* __restrict__ w_hat,
            const float* __restrict__ dw16,
            const float* __restrict__ w_gt,
            const float* __restrict__ w_mean,
            const float* __restrict__ w_std) {
    const int lane = threadIdx.x & 31;
    const int warp_global = (blockIdx.x * blockDim.x + threadIdx.x) >> 5;
    // 65536 warps total: n = sequence, jl = 32-step unit within sequence
    const int n  = warp_global >> 9;    // / 512
    const int jl = warp_global & 511;

    const int t  = (n << 14) + (jl << 5) + lane;   // global timestep index
    const int idx = t * 3;

    // ---- load w_hat (needed by both gyro chain and gnll) ----
    float whx = w_hat[idx + 0];
    float why = w_hat[idx + 1];
    float whz = w_hat[idx + 2];

    // ---- gaussian NLL (elementwise, all lanes) ----
    double acc = 0.0;
    {
        float gx = w_gt[idx+0] - whx - w_mean[idx+0];
        float gy = w_gt[idx+1] - why - w_mean[idx+1];
        float gz = w_gt[idx+2] - whz - w_mean[idx+2];
        float s0 = w_std[idx+0], s1 = w_std[idx+1], s2 = w_std[idx+2];
        float v0 = s0*s0; if (v0 < 1e-6f) v0 = 1e-6f;
        float v1 = s1*s1; if (v1 < 1e-6f) v1 = 1e-6f;
        float v2 = s2*s2; if (v2 < 1e-6f) v2 = 1e-6f;
        float nll = (logf(v0) + gx*gx/v0)
                  + (logf(v1) + gy*gy/v1)
                  + (logf(v2) + gz*gz/v2);
        acc = (double)nll * CNLL;
    }

    // ---- gyro chain: R_l = exp(DT * w_hat) ----
    Mat3 R = so3_exp(0.005f*whx, 0.005f*why, 0.005f*whz);

    // binary-tree fold (same bracketing as reference _pairwise iterations)
#pragma unroll
    for (int s = 1; s <= 8; s <<= 1) {
        Mat3 T = shfl_down_mat(R, s);
        R = mat_mul(R, T);
    }
    // lane 0: Q0 = prod R[0..15]; lane 16: Q1 = prod R[16..31]

    // P at sampled positions: dw16[n, 32*jl] (lane 0), dw16[n, 32*jl+16] (lane 16)
    float dx = 0.0f, dy = 0.0f, dz = 0.0f;
    if ((lane & 15) == 0) {
        dx = dw16[idx + 0]; dy = dw16[idx + 1]; dz = dw16[idx + 2];
    }
    Mat3 P = so3_exp(dx, dy, dz);   // identity on unused lanes

    Mat3 Q1s = shfl_idx_mat(R, 16);
    Mat3 P1s = shfl_idx_mat(P, 16);

    if ((lane & 15) == 0 && lane < 32) {
        int il = 2*jl + (lane >> 4);          // 16-level index within sequence
        if (il >= 5) {
            Mat3 M = mat_tmul(R, P);          // Q^T P
            float r[3]; so3_log_vec(M, r);
            acc += (double)huber3(r) * C16;
        }
    }
    if (lane == 0 && jl >= 5) {
        Mat3 Qp = mat_mul(R, Q1s);            // product of 32
        Mat3 Pp = mat_mul(P, P1s);
        Mat3 M  = mat_tmul(Qp, Pp);
        float r[3]; so3_log_vec(M, r);
        acc += (double)huber3(r) * C32;
    }

    // ---- reduce: warp -> block -> 64-way banked global accumulators ----
#pragma unroll
    for (int s = 16; s > 0; s >>= 1)
        acc += __shfl_down_sync(FULL_MASK, acc, s);

    __shared__ double ssum[8];
    if (lane == 0) ssum[threadIdx.x >> 5] = acc;
    __syncthreads();
    if (threadIdx.x < 8) {
        double v = ssum[threadIdx.x];
#pragma unroll
        for (int s = 4; s > 0; s >>= 1)
            v += __shfl_down_sync(0xFFu, v, s);
        if (threadIdx.x == 0)
            atomicAdd(&g_acc[blockIdx.x & 63], v);
    }
}

__global__ void finalize_kernel(float* __restrict__ out) {
    if (threadIdx.x == 0) {
        double s = 0.0;
#pragma unroll
        for (int i = 0; i < 64; i++) s += g_acc[i];
        out[0] = (float)s;
    }
}

extern "C" void kernel_launch(void* const* d_in, const int* in_sizes, int n_in,
                              void* d_out, int out_size) {
    const float* w_hat  = (const float*)d_in[0];
    const float* dw16   = (const float*)d_in[1];
    const float* w_gt   = (const float*)d_in[2];
    const float* w_mean = (const float*)d_in[3];
    const float* w_std  = (const float*)d_in[4];
    float* out = (float*)d_out;

    zero_acc_kernel<<<1, 64>>>();
    // 65536 warps -> 8192 blocks of 256 threads (8 warps)
    loss_kernel<<<8192, 256>>>(w_hat, dw16, w_gt, w_mean, w_std);
    finalize_kernel<<<1, 32>>>(out);
}

// round 5
// speedup vs baseline: 2.4713x; 2.4713x over previous
#include <cuda_runtime.h>

// ---------------------------------------------------------------------------
// DGLossVer2: fused gyro (SO3 chain) + gaussian-NLL scalar loss.
// N=128 seqs, T=16384 steps, 3 ch. One warp handles 128 consecutive steps:
//   each lane: 4 sequential exp+matmul (product of its 4 steps)
//   3 shfl_down fold rounds -> 16-products at lanes %4==0, 32-products at %8==0
//   residual logs vs exp(dw16[::16]) (8 sample lanes/warp), GNLL fused.
// Float accumulation; double only in the tiny finalize reduce.
// ---------------------------------------------------------------------------

#define FULL_MASK 0xFFFFFFFFu

// scale constants (means pre-folded)
#define C16F  (25.0f   / 391296.0f)    // W*H^2 / (128*1019*3)
#define C32F  (6.25f   / 194688.0f)    // W*H^2/4 / (128*507*3)
#define CNLLF (0.5f    / 6291456.0f)   // 0.5 / (128*16384*3)

static __device__ float g_part[2048];

struct Mat3 { float a[9]; };   // row-major

__device__ __forceinline__ Mat3 mat_mul(const Mat3& A, const Mat3& B) {
    Mat3 C;
#pragma unroll
    for (int i = 0; i < 3; i++)
#pragma unroll
        for (int j = 0; j < 3; j++)
            C.a[3*i+j] = A.a[3*i+0]*B.a[0+j] + A.a[3*i+1]*B.a[3+j] + A.a[3*i+2]*B.a[6+j];
    return C;
}

// C = A^T * B
__device__ __forceinline__ Mat3 mat_tmul(const Mat3& A, const Mat3& B) {
    Mat3 C;
#pragma unroll
    for (int i = 0; i < 3; i++)
#pragma unroll
        for (int j = 0; j < 3; j++)
            C.a[3*i+j] = A.a[0+i]*B.a[0+j] + A.a[3+i]*B.a[3+j] + A.a[6+i]*B.a[6+j];
    return C;
}

__device__ __forceinline__ Mat3 shfl_down_mat(const Mat3& M, int d) {
    Mat3 R;
#pragma unroll
    for (int i = 0; i < 9; i++) R.a[i] = __shfl_down_sync(FULL_MASK, M.a[i], d);
    return R;
}

// Build rotation from sin_t = sin(a)/a, cos_t = (1-cos(a))/a^2
__device__ __forceinline__ Mat3 rot_from(float x, float y, float z,
                                         float sin_t, float cos_t) {
    Mat3 R;
    float xy = x*y, xz = x*z, yz = y*z;
    R.a[0] = 1.0f - cos_t * (y*y + z*z);
    R.a[1] = -sin_t*z + cos_t*xy;
    R.a[2] =  sin_t*y + cos_t*xz;
    R.a[3] =  sin_t*z + cos_t*xy;
    R.a[4] = 1.0f - cos_t * (x*x + z*z);
    R.a[5] = -sin_t*x + cos_t*yz;
    R.a[6] = -sin_t*y + cos_t*xz;
    R.a[7] =  sin_t*x + cos_t*yz;
    R.a[8] = 1.0f - cos_t * (x*x + y*y);
    return R;
}

// angles <= ~0.04 rad: 2-term Taylor, error ~1e-12
__device__ __forceinline__ Mat3 so3_exp_small(float x, float y, float z) {
    float a2 = x*x + y*y + z*z;
    float sin_t = 1.0f + a2 * (-(1.0f/6.0f)  + a2 * (1.0f/120.0f));
    float cos_t = 0.5f + a2 * (-(1.0f/24.0f) + a2 * (1.0f/720.0f));
    return rot_from(x, y, z, sin_t, cos_t);
}

// full-range (dw16, angle ~1.7 rad typical)
__device__ __forceinline__ Mat3 so3_exp_full(float x, float y, float z) {
    float a2 = x*x + y*y + z*z;
    float sin_t, cos_t;
    if (a2 < 1e-12f) {
        sin_t = 1.0f - a2 * (1.0f/6.0f);
        cos_t = 0.5f - a2 * (1.0f/24.0f);
    } else {
        float a = sqrtf(a2);
        sin_t = __sinf(a) / a;
        cos_t = (1.0f - __cosf(a)) / a2;
    }
    return rot_from(x, y, z, sin_t, cos_t);
}

// reference clips cos into [-1+1e-6, 1-1e-6]; sin(acos(c)) = sqrt(1-c^2)
__device__ __forceinline__ void so3_log_vec(const Mat3& R, float r[3]) {
    float tr = R.a[0] + R.a[4] + R.a[8];
    float c = 0.5f * (tr - 1.0f);
    c = fminf(fmaxf(c, -1.0f + 1e-6f), 1.0f - 1e-6f);
    float factor = 0.5f * acosf(c) * rsqrtf((1.0f - c) * (1.0f + c));
    r[0] = factor * (R.a[7] - R.a[5]);
    r[1] = factor * (R.a[2] - R.a[6]);
    r[2] = factor * (R.a[3] - R.a[1]);
}

__device__ __forceinline__ float huber3(const float r[3]) {
    float s = 0.0f;
#pragma unroll
    for (int c = 0; c < 3; c++) {
        float x = fabsf(r[c]) * 200.0f;      // 1/HUBER
        s += (x < 1.0f) ? 0.5f * x * x : x - 0.5f;
    }
    return s;
}

__device__ __forceinline__ void load12(const float* __restrict__ p, int base, float v[12]) {
    const float4* p4 = reinterpret_cast<const float4*>(p + base);
    *reinterpret_cast<float4*>(&v[0]) = p4[0];
    *reinterpret_cast<float4*>(&v[4]) = p4[1];
    *reinterpret_cast<float4*>(&v[8]) = p4[2];
}

__global__ void __launch_bounds__(256)
loss_kernel(const float* __restrict__ w_hat,
            const float* __restrict__ dw16,
            const float* __restrict__ w_gt,
            const float* __restrict__ w_mean,
            const float* __restrict__ w_std) {
    const int lane = threadIdx.x & 31;
    const int w = blockIdx.x * 8 + (threadIdx.x >> 5);   // global warp, 16384 total
    const int n  = w >> 7;                               // 128 warps per sequence
    const int jw = w & 127;
    const int t0 = (n << 14) + (jw << 7) + (lane << 2);  // this thread's first step
    const int base = t0 * 3;                             // float offset (48B aligned)

    // ---- loads (3x LDG.128 per array) ----
    float h[12], g[12], m[12], s[12];
    load12(w_hat,  base, h);
    load12(w_gt,   base, g);
    load12(w_mean, base, m);
    load12(w_std,  base, s);

    // ---- gaussian NLL over 4 steps (12 components) ----
    float gn = 0.0f;
#pragma unroll
    for (int c = 0; c < 12; c++) {
        float gap = g[c] - h[c] - m[c];
        float v = s[c] * s[c];
        v = fmaxf(v, 1e-6f);
        gn += __logf(v) + __fdividef(gap * gap, v);
    }
    float accf = gn * CNLLF;

    // ---- gyro chain: product of this thread's 4 steps ----
    Mat3 M = so3_exp_small(0.005f*h[0], 0.005f*h[1], 0.005f*h[2]);
#pragma unroll
    for (int st = 1; st < 4; st++) {
        Mat3 R = so3_exp_small(0.005f*h[3*st], 0.005f*h[3*st+1], 0.005f*h[3*st+2]);
        M = mat_mul(M, R);
    }

    // ---- warp folds: 8-prod, 16-prod (lanes %4==0), 32-prod (lanes %8==0) ----
    {
        Mat3 T = shfl_down_mat(M, 1); M = mat_mul(M, T);
    }
    {
        Mat3 T = shfl_down_mat(M, 2); M = mat_mul(M, T);
    }
    Mat3 T4 = shfl_down_mat(M, 4);
    Mat3 Q32 = mat_mul(M, T4);         // valid at lanes %8==0

    // ---- P = exp(dw16) at sample lanes (t0 % 16 == 0 <=> lane%4==0) ----
    const bool samp = ((lane & 3) == 0);
    float dx = 0.0f, dy = 0.0f, dz = 0.0f;
    if (samp) { dx = dw16[base]; dy = dw16[base+1]; dz = dw16[base+2]; }
    Mat3 P = so3_exp_full(dx, dy, dz);
    Mat3 Pn = shfl_down_mat(P, 4);

    // ---- 16-level residual ----
    if (samp) {
        int il = (jw << 3) + (lane >> 2);
        if (il >= 5) {
            Mat3 Mr = mat_tmul(M, P);     // Q16^T P
            float r[3]; so3_log_vec(Mr, r);
            accf += huber3(r) * C16F;
        }
    }
    // ---- 32-level residual ----
    if ((lane & 7) == 0) {
        int i32 = (jw << 2) + (lane >> 3);
        if (i32 >= 5) {
            Mat3 P2 = mat_mul(P, Pn);
            Mat3 Mr = mat_tmul(Q32, P2);
            float r[3]; so3_log_vec(Mr, r);
            accf += huber3(r) * C32F;
        }
    }

    // ---- reduce: warp -> block -> per-block partial (no atomics, no zeroing) ----
#pragma unroll
    for (int d = 16; d > 0; d >>= 1)
        accf += __shfl_down_sync(FULL_MASK, accf, d);

    __shared__ float ssum[8];
    if (lane == 0) ssum[threadIdx.x >> 5] = accf;
    __syncthreads();
    if (threadIdx.x == 0) {
        float t = 0.0f;
#pragma unroll
        for (int i = 0; i < 8; i++) t += ssum[i];
        g_part[blockIdx.x] = t;
    }
}

__global__ void __launch_bounds__(256)
finalize_kernel(float* __restrict__ out) {
    double v = 0.0;
    for (int i = threadIdx.x; i < 2048; i += 256) v += (double)g_part[i];
#pragma unroll
    for (int d = 16; d > 0; d >>= 1)
        v += __shfl_down_sync(FULL_MASK, v, d);
    __shared__ double sd[8];
    const int lane = threadIdx.x & 31;
    if (lane == 0) sd[threadIdx.x >> 5] = v;
    __syncthreads();
    if (threadIdx.x == 0) {
        double t = 0.0;
#pragma unroll
        for (int i = 0; i < 8; i++) t += sd[i];
        out[0] = (float)t;
    }
}

extern "C" void kernel_launch(void* const* d_in, const int* in_sizes, int n_in,
                              void* d_out, int out_size) {
    const float* w_hat  = (const float*)d_in[0];
    const float* dw16   = (const float*)d_in[1];
    const float* w_gt   = (const float*)d_in[2];
    const float* w_mean = (const float*)d_in[3];
    const float* w_std  = (const float*)d_in[4];
    float* out = (float*)d_out;

    // 16384 warps -> 2048 blocks x 256 threads
    loss_kernel<<<2048, 256>>>(w_hat, dw16, w_gt, w_mean, w_std);
    finalize_kernel<<<1, 256>>>(out);
}

// round 6
// speedup vs baseline: 2.7687x; 1.1203x over previous
#include <cuda_runtime.h>

// ---------------------------------------------------------------------------
// DGLossVer2: fused gyro (SO3 chain) + gaussian-NLL scalar loss, ONE launch.
// N=128 seqs, T=16384 steps, 3 ch. One warp handles 256 consecutive steps:
//   each lane: product of its 8 steps (7 in-thread matmuls)
//   2 shfl_down fold rounds -> 16-products at even lanes, 32-products at %4==0
//   residual logs vs exp(dw16[::16]), GNLL fused (grouped logs).
// Last block performs the final reduction (threadfence pattern): no 2nd kernel.
// ---------------------------------------------------------------------------

#define FULL_MASK 0xFFFFFFFFu

#define C16F  (25.0f / 391296.0f)    // W*H^2 / (128*1019*3)
#define C32F  (6.25f / 194688.0f)    // W*H^2/4 / (128*507*3)
#define CNLLF (0.5f  / 6291456.0f)   // 0.5 / (128*16384*3)

#define NBLK 1024

static __device__ float g_part[NBLK];
static __device__ unsigned int g_ticket;   // zero-init; last block resets to 0

struct Mat3 { float a[9]; };   // row-major

__device__ __forceinline__ Mat3 mat_mul(const Mat3& A, const Mat3& B) {
    Mat3 C;
#pragma unroll
    for (int i = 0; i < 3; i++)
#pragma unroll
        for (int j = 0; j < 3; j++)
            C.a[3*i+j] = A.a[3*i+0]*B.a[0+j] + A.a[3*i+1]*B.a[3+j] + A.a[3*i+2]*B.a[6+j];
    return C;
}

// C = A^T * B
__device__ __forceinline__ Mat3 mat_tmul(const Mat3& A, const Mat3& B) {
    Mat3 C;
#pragma unroll
    for (int i = 0; i < 3; i++)
#pragma unroll
        for (int j = 0; j < 3; j++)
            C.a[3*i+j] = A.a[0+i]*B.a[0+j] + A.a[3+i]*B.a[3+j] + A.a[6+i]*B.a[6+j];
    return C;
}

__device__ __forceinline__ Mat3 shfl_down_mat(const Mat3& M, int d) {
    Mat3 R;
#pragma unroll
    for (int i = 0; i < 9; i++) R.a[i] = __shfl_down_sync(FULL_MASK, M.a[i], d);
    return R;
}

__device__ __forceinline__ Mat3 rot_from(float x, float y, float z,
                                         float sin_t, float cos_t) {
    Mat3 R;
    float xy = x*y, xz = x*z, yz = y*z;
    R.a[0] = 1.0f - cos_t * (y*y + z*z);
    R.a[1] = -sin_t*z + cos_t*xy;
    R.a[2] =  sin_t*y + cos_t*xz;
    R.a[3] =  sin_t*z + cos_t*xy;
    R.a[4] = 1.0f - cos_t * (x*x + z*z);
    R.a[5] = -sin_t*x + cos_t*yz;
    R.a[6] = -sin_t*y + cos_t*xz;
    R.a[7] =  sin_t*x + cos_t*yz;
    R.a[8] = 1.0f - cos_t * (x*x + y*y);
    return R;
}

// angles <= ~0.04 rad: Taylor, error ~1e-12
__device__ __forceinline__ Mat3 so3_exp_small(float x, float y, float z) {
    float a2 = x*x + y*y + z*z;
    float sin_t = 1.0f + a2 * (-(1.0f/6.0f)  + a2 * (1.0f/120.0f));
    float cos_t = 0.5f + a2 * (-(1.0f/24.0f) + a2 * (1.0f/720.0f));
    return rot_from(x, y, z, sin_t, cos_t);
}

// full-range (dw16 samples)
__device__ __forceinline__ Mat3 so3_exp_full(float x, float y, float z) {
    float a2 = x*x + y*y + z*z;
    float sin_t, cos_t;
    if (a2 < 1e-12f) {
        sin_t = 1.0f - a2 * (1.0f/6.0f);
        cos_t = 0.5f - a2 * (1.0f/24.0f);
    } else {
        float a = sqrtf(a2);
        sin_t = __sinf(a) / a;
        cos_t = (1.0f - __cosf(a)) / a2;
    }
    return rot_from(x, y, z, sin_t, cos_t);
}

// reference clips cos; sin(acos(c)) = sqrt(1-c^2)
__device__ __forceinline__ void so3_log_vec(const Mat3& R, float r[3]) {
    float tr = R.a[0] + R.a[4] + R.a[8];
    float c = 0.5f * (tr - 1.0f);
    c = fminf(fmaxf(c, -1.0f + 1e-6f), 1.0f - 1e-6f);
    float factor = 0.5f * acosf(c) * rsqrtf((1.0f - c) * (1.0f + c));
    r[0] = factor * (R.a[7] - R.a[5]);
    r[1] = factor * (R.a[2] - R.a[6]);
    r[2] = factor * (R.a[3] - R.a[1]);
}

__device__ __forceinline__ float huber3(const float r[3]) {
    float s = 0.0f;
#pragma unroll
    for (int c = 0; c < 3; c++) {
        float x = fabsf(r[c]) * 200.0f;      // 1/HUBER
        s += (x < 1.0f) ? 0.5f * x * x : x - 0.5f;
    }
    return s;
}

__global__ void __launch_bounds__(256)
loss_kernel(const float* __restrict__ w_hat,
            const float* __restrict__ dw16,
            const float* __restrict__ w_gt,
            const float* __restrict__ w_mean,
            const float* __restrict__ w_std,
            float* __restrict__ out) {
    const int lane = threadIdx.x & 31;
    const int w = blockIdx.x * 8 + (threadIdx.x >> 5);   // 8192 warps total
    const int n  = w >> 6;                               // 64 warps per sequence
    const int jw = w & 63;
    const int t0 = (n << 14) + (jw << 8) + (lane << 3);  // first of 8 steps
    const int base = t0 * 3;                             // 96B-aligned float offset

    // ---- w_hat: 6x LDG.128 (24 floats = 8 steps) ----
    float h[24];
    {
        const float4* p4 = reinterpret_cast<const float4*>(w_hat + base);
#pragma unroll
        for (int c = 0; c < 6; c++)
            *reinterpret_cast<float4*>(&h[4*c]) = p4[c];
    }

    // ---- gaussian NLL, streamed in float4 chunks; logs grouped by 4 ----
    float accf = 0.0f;
    {
        const float4* g4 = reinterpret_cast<const float4*>(w_gt   + base);
        const float4* m4 = reinterpret_cast<const float4*>(w_mean + base);
        const float4* s4 = reinterpret_cast<const float4*>(w_std  + base);
        float gn = 0.0f;
#pragma unroll
        for (int c = 0; c < 6; c++) {
            float4 gv = g4[c], mv = m4[c], sv = s4[c];
            float v0 = fmaxf(sv.x*sv.x, 1e-6f);
            float v1 = fmaxf(sv.y*sv.y, 1e-6f);
            float v2 = fmaxf(sv.z*sv.z, 1e-6f);
            float v3 = fmaxf(sv.w*sv.w, 1e-6f);
            float d0 = gv.x - h[4*c+0] - mv.x;
            float d1 = gv.y - h[4*c+1] - mv.y;
            float d2 = gv.z - h[4*c+2] - mv.z;
            float d3 = gv.w - h[4*c+3] - mv.w;
            gn += __fdividef(d0*d0, v0) + __fdividef(d1*d1, v1)
                + __fdividef(d2*d2, v2) + __fdividef(d3*d3, v3);
            gn += __logf(v0 * v1 * v2 * v3);   // grouped log, min 1e-24 > FLT_MIN
        }
        accf = gn * CNLLF;
    }

    // ---- gyro chain: product of this thread's 8 steps ----
    Mat3 M = so3_exp_small(0.005f*h[0], 0.005f*h[1], 0.005f*h[2]);
#pragma unroll
    for (int st = 1; st < 8; st++) {
        Mat3 R = so3_exp_small(0.005f*h[3*st], 0.005f*h[3*st+1], 0.005f*h[3*st+2]);
        M = mat_mul(M, R);
    }

    // ---- warp folds: 16-prod at even lanes, 32-prod at lanes %4==0 ----
    {
        Mat3 T = shfl_down_mat(M, 1); M = mat_mul(M, T);   // 16-product
    }
    Mat3 T2 = shfl_down_mat(M, 2);
    Mat3 Q32 = mat_mul(M, T2);                             // 32-product (%4==0)

    // ---- P = exp(dw16) at sample lanes (t0 % 16 == 0 <=> even lane) ----
    const bool samp = ((lane & 1) == 0);
    float dx = 0.0f, dy = 0.0f, dz = 0.0f;
    if (samp) { dx = dw16[base]; dy = dw16[base+1]; dz = dw16[base+2]; }
    Mat3 P = so3_exp_full(dx, dy, dz);                     // identity on odd lanes
    Mat3 Pn = shfl_down_mat(P, 2);

    // ---- 16-level residual (16 per warp) ----
    if (samp) {
        int il = (jw << 4) + (lane >> 1);
        if (il >= 5) {
            Mat3 Mr = mat_tmul(M, P);                      // Q16^T P
            float r[3]; so3_log_vec(Mr, r);
            accf += huber3(r) * C16F;
        }
    }
    // ---- 32-level residual (8 per warp) ----
    if ((lane & 3) == 0) {
        int i32 = (jw << 3) + (lane >> 2);
        if (i32 >= 5) {
            Mat3 P2 = mat_mul(P, Pn);
            Mat3 Mr = mat_tmul(Q32, P2);
            float r[3]; so3_log_vec(Mr, r);
            accf += huber3(r) * C32F;
        }
    }

    // ---- block reduce ----
#pragma unroll
    for (int d = 16; d > 0; d >>= 1)
        accf += __shfl_down_sync(FULL_MASK, accf, d);

    __shared__ float ssum[8];
    __shared__ bool s_last;
    if (lane == 0) ssum[threadIdx.x >> 5] = accf;
    __syncthreads();
    if (threadIdx.x == 0) {
        float t = 0.0f;
#pragma unroll
        for (int i = 0; i < 8; i++) t += ssum[i];
        g_part[blockIdx.x] = t;
        __threadfence();
        unsigned int tk = atomicAdd(&g_ticket, 1u);
        s_last = (tk == NBLK - 1u);
    }
    __syncthreads();

    // ---- last block: final reduction + output + ticket reset ----
    if (s_last) {
        double v = 0.0;
#pragma unroll
        for (int i = 0; i < NBLK / 256; i++)
            v += (double)g_part[threadIdx.x + 256 * i];
#pragma unroll
        for (int d = 16; d > 0; d >>= 1)
            v += __shfl_down_sync(FULL_MASK, v, d);
        __shared__ double sd[8];
        if (lane == 0) sd[threadIdx.x >> 5] = v;
        __syncthreads();
        if (threadIdx.x == 0) {
            double t = 0.0;
#pragma unroll
            for (int i = 0; i < 8; i++) t += sd[i];
            out[0] = (float)t;
            g_ticket = 0;          // reset for next graph replay
        }
    }
}

extern "C" void kernel_launch(void* const* d_in, const int* in_sizes, int n_in,
                              void* d_out, int out_size) {
    const float* w_hat  = (const float*)d_in[0];
    const float* dw16   = (const float*)d_in[1];
    const float* w_gt   = (const float*)d_in[2];
    const float* w_mean = (const float*)d_in[3];
    const float* w_std  = (const float*)d_in[4];
    float* out = (float*)d_out;

    // 8192 warps -> 1024 blocks x 256 threads, single launch
    loss_kernel<<<NBLK, 256>>>(w_hat, dw16, w_gt, w_mean, w_std, out);
}